// round 12
// baseline (speedup 1.0000x reference)
#include <cuda_runtime.h>
#include <stdint.h>

// ---------------------------------------------------------------------------
// DoctoralLoss fused single-kernel: MC aleatoric CE (T=100, exact JAX
// partitionable threefry + XLA erfinv) + 0.5*pinball(0.5) + 0.1*mean(exp(lv)).
// f32x2-packed float math (2 t-samples/iter), block-local dtype sniff,
// ticket-based last-block finalize.
// ---------------------------------------------------------------------------

#define T_SAMPLES 100
#define B_ROWS    131072
#define C_CLASSES 3
#define NCHUNK    5
#define TCHUNK    (T_SAMPLES / NCHUNK)    // 20
#define NPAIR     (TCHUNK / 2)            // 10
#define TPB       128
#define NTHREADS  (B_ROWS * NCHUNK)       // 655360
#define NBLOCKS   (NTHREADS / TPB)        // 5120
#define STRIDE    (B_ROWS * C_CLASSES)    // 393216

typedef unsigned long long u64_t;

__device__ double       g_partials[NBLOCKS];
__device__ unsigned int g_ticket = 0;

// ---------------- f32x2 helpers ----------------
__device__ __forceinline__ u64_t pk2(float lo, float hi) {
    u64_t r; asm("mov.b64 %0, {%1, %2};" : "=l"(r) : "f"(lo), "f"(hi)); return r;
}
__device__ __forceinline__ void upk2(u64_t v, float& lo, float& hi) {
    asm("mov.b64 {%0, %1}, %2;" : "=f"(lo), "=f"(hi) : "l"(v));
}
__device__ __forceinline__ u64_t fma2(u64_t a, u64_t b, u64_t c) {
    u64_t d; asm("fma.rn.f32x2 %0, %1, %2, %3;" : "=l"(d) : "l"(a), "l"(b), "l"(c)); return d;
}
__device__ __forceinline__ u64_t add2(u64_t a, u64_t b) {
    u64_t d; asm("add.rn.f32x2 %0, %1, %2;" : "=l"(d) : "l"(a), "l"(b)); return d;
}
__device__ __forceinline__ u64_t mul2(u64_t a, u64_t b) {
    u64_t d; asm("mul.rn.f32x2 %0, %1, %2;" : "=l"(d) : "l"(a), "l"(b)); return d;
}
// compile-time packable broadcast constant
__device__ __forceinline__ u64_t pkc(float v) {
    unsigned u = __float_as_uint(v);
    return ((u64_t)u << 32) | (u64_t)u;
}
__device__ __forceinline__ float ex2f(float x) {
    float r; asm("ex2.approx.f32 %0, %1;" : "=f"(r) : "f"(x)); return r;
}
__device__ __forceinline__ float lg2f(float x) {
    float r; asm("lg2.approx.f32 %0, %1;" : "=f"(r) : "f"(x)); return r;
}
__device__ __forceinline__ uint32_t rotl32(uint32_t v, int s) {
    return __funnelshift_l(v, v, s);
}

// ---------------- threefry2x32, key=(0,42), counter=(0,i), out = x0^x1 ------
__device__ __forceinline__ uint32_t threefry_bits(uint32_t i) {
    const uint32_t ks0 = 0u;
    const uint32_t ks1 = 42u;
    const uint32_t ks2 = 0x1BD11BDAu ^ 0u ^ 42u;

    uint32_t x0 = 0u + ks0;
    uint32_t x1 = i + ks1;

#define TF_ROUND(r) { x0 += x1; x1 = rotl32(x1, (r)); x1 ^= x0; }
#define TF_4ROUNDS(a,b,c,d) TF_ROUND(a) TF_ROUND(b) TF_ROUND(c) TF_ROUND(d)
    TF_4ROUNDS(13, 15, 26, 6)
    x0 += ks1; x1 += ks2 + 1u;
    TF_4ROUNDS(17, 29, 16, 24)
    x0 += ks2; x1 += ks0 + 2u;
    TF_4ROUNDS(13, 15, 26, 6)
    x0 += ks0; x1 += ks1 + 3u;
    TF_4ROUNDS(17, 29, 16, 24)
    x0 += ks1; x1 += ks2 + 4u;
    TF_4ROUNDS(13, 15, 26, 6)
    x0 += ks2; x1 += ks0 + 5u;
#undef TF_4ROUNDS
#undef TF_ROUND
    return x0 ^ x1;
}

// sqrt(2) folded into erfinv coefficients (<=2ulp per-sample vs reference)
#define SQ2 1.4142135623730951
#define CP(x) pkc((float)((x) * SQ2))

// rare-branch (w >= 5) scalar erfinv * sqrt2, times u
__device__ __forceinline__ float erfinv_rare(float w, float u) {
    float v = sqrtf(w) - 3.0f;
    float p =            (float)(-0.000200214257 * SQ2);
    p = fmaf(p, v,        (float)(0.000100950558 * SQ2));
    p = fmaf(p, v,        (float)(0.00134934322  * SQ2));
    p = fmaf(p, v,        (float)(-0.00367342844 * SQ2));
    p = fmaf(p, v,        (float)(0.00573950773  * SQ2));
    p = fmaf(p, v,        (float)(-0.0076224613  * SQ2));
    p = fmaf(p, v,        (float)(0.00943887047  * SQ2));
    p = fmaf(p, v,        (float)(1.00167406     * SQ2));
    p = fmaf(p, v,        (float)(2.83297682     * SQ2));
    return p * u;
}

// two threefry outputs -> packed pair of N(0,1) samples (sqrt2 folded)
__device__ __forceinline__ u64_t norm_pair(uint32_t ba, uint32_t bb) {
    const u64_t C_NEG1 = pkc(-1.0f);
    const u64_t C_TWO  = pkc(2.0f);
    const u64_t C_LO   = pkc(-0.99999994f);     // nextafter(-1,0)
    const u64_t C_ONE  = pkc(1.0f);
    const u64_t C_MLN2 = pkc((float)(-0.6931471805599453));
    const u64_t C_M25  = pkc(-2.5f);

    float fa = __uint_as_float((ba >> 9) | 0x3f800000u);   // [1,2)
    float fb = __uint_as_float((bb >> 9) | 0x3f800000u);
    u64_t F   = pk2(fa, fb);
    u64_t FM1 = add2(F, C_NEG1);                 // exact, in [0,1)
    u64_t U   = fma2(FM1, C_TWO, C_LO);          // uniform in [LO, 1); max(LO,.) redundant
    u64_t AP  = add2(U, C_ONE);                  // 1+x
    u64_t AM  = fma2(U, C_NEG1, C_ONE);          // 1-x (single rounding)
    u64_t TT  = mul2(AP, AM);                    // (1-x)(1+x) > 0
    float t0, t1; upk2(TT, t0, t1);
    u64_t LG  = pk2(lg2f(t0), lg2f(t1));
    u64_t W   = mul2(LG, C_MLN2);                // w = -log(t)
    u64_t S   = add2(W, C_M25);
    u64_t P   = CP(2.81022636e-08);
    P = fma2(P, S, CP(3.43273939e-07));
    P = fma2(P, S, CP(-3.5233877e-06));
    P = fma2(P, S, CP(-4.39150654e-06));
    P = fma2(P, S, CP(0.00021858087));
    P = fma2(P, S, CP(-0.00125372503));
    P = fma2(P, S, CP(-0.00417768164));
    P = fma2(P, S, CP(0.246640727));
    P = fma2(P, S, CP(1.50140941));
    u64_t R = mul2(P, U);                        // N(0,1) pair (sqrt2 folded)

    // rare tail: t <= e^-5  <=>  w >= 5
    const float T_TH = 6.7379470e-03f;
    if (__builtin_expect(__any_sync(0xffffffffu, fminf(t0, t1) <= T_TH), 0)) {
        float r0, r1, u0, u1, w0, w1;
        upk2(R, r0, r1); upk2(U, u0, u1); upk2(W, w0, w1);
        if (t0 <= T_TH) r0 = erfinv_rare(w0, u0);
        if (t1 <= T_TH) r1 = erfinv_rare(w1, u1);
        R = pk2(r0, r1);
    }
    return R;
}

__global__ __launch_bounds__(TPB) void loss_kernel(
    const float* __restrict__ logits,
    const float* __restrict__ log_var,
    const float* __restrict__ p_win,
    const int*   __restrict__ tgt32,
    float*       __restrict__ out)
{
    // ---- block-local dtype sniff: int64 targets have zero hi-words ----
    int probe = tgt32[2 * threadIdx.x + 1];
    bool is64 = (__syncthreads_count(probe != 0) == 0);

    int gid   = blockIdx.x * TPB + threadIdx.x;
    int b     = gid & (B_ROWS - 1);
    int chunk = gid >> 17;                        // B_ROWS = 2^17

    float l0 = logits[3 * b + 0];
    float l1 = logits[3 * b + 1];
    float l2 = logits[3 * b + 2];
    float lv   = log_var[b];
    float stdv = expf(0.5f * lv);
    int   tgt  = is64 ? tgt32[2 * b] : tgt32[b];

    const u64_t STD2  = pk2(stdv, stdv);
    const u64_t L02   = pk2(l0, l0);
    const u64_t L12   = pk2(l1, l1);
    const u64_t L22   = pk2(l2, l2);
    const u64_t C_NEG1 = pkc(-1.0f);
    const u64_t C_L2E  = pkc((float)1.4426950408889634);   // log2(e), same as __expf
    const float LN2F   = (float)0.6931471805599453;

    float accA = 0.0f, accB = 0.0f;
    uint32_t ctr = (uint32_t)(chunk * TCHUNK) * (uint32_t)STRIDE + (uint32_t)b * 3u;

    #pragma unroll 1
    for (int j = 0; j < NPAIR; ++j) {
        uint32_t iA = ctr;
        uint32_t iB = ctr + (uint32_t)STRIDE;
        ctr += 2u * (uint32_t)STRIDE;

        u64_t N0 = norm_pair(threefry_bits(iA),      threefry_bits(iB));
        u64_t N1 = norm_pair(threefry_bits(iA + 1u), threefry_bits(iB + 1u));
        u64_t N2 = norm_pair(threefry_bits(iA + 2u), threefry_bits(iB + 2u));

        u64_t D0 = fma2(N0, STD2, L02);
        u64_t D1 = fma2(N1, STD2, L12);
        u64_t D2 = fma2(N2, STD2, L22);

        float d0a, d0b, d1a, d1b, d2a, d2b;
        upk2(D0, d0a, d0b); upk2(D1, d1a, d1b); upk2(D2, d2a, d2b);
        float ma = fmaxf(d0a, fmaxf(d1a, d2a));
        float mb = fmaxf(d0b, fmaxf(d1b, d2b));
        u64_t M2v = pk2(ma, mb);

        u64_t E0 = mul2(fma2(M2v, C_NEG1, D0), C_L2E);   // (d-m)*log2e
        u64_t E1 = mul2(fma2(M2v, C_NEG1, D1), C_L2E);
        u64_t E2 = mul2(fma2(M2v, C_NEG1, D2), C_L2E);
        float e0a, e0b, e1a, e1b, e2a, e2b;
        upk2(E0, e0a, e0b); upk2(E1, e1a, e1b); upk2(E2, e2a, e2b);

        float sa = ex2f(e0a) + ex2f(e1a) + ex2f(e2a);
        float sb = ex2f(e0b) + ex2f(e1b) + ex2f(e2b);
        float lsea = fmaf(lg2f(sa), LN2F, ma);
        float lseb = fmaf(lg2f(sb), LN2F, mb);

        float dta = (tgt == 0) ? d0a : ((tgt == 1) ? d1a : d2a);
        float dtb = (tgt == 0) ? d0b : ((tgt == 1) ? d1b : d2b);
        accA += (lsea - dta);
        accB += (lseb - dtb);
    }

    double part = ((double)accA + (double)accB)
                * (1.0 / ((double)T_SAMPLES * (double)B_ROWS));

    if (chunk == 0) {
        int pred = 0; float mm = l0;
        if (l1 > mm) { mm = l1; pred = 1; }
        if (l2 > mm) { mm = l2; pred = 2; }
        float corr = (pred == tgt) ? 1.0f : 0.0f;
        float e    = corr - p_win[b];
        float pin  = 0.5f * fabsf(e);            // pinball, Q = 0.5
        part += ((double)(0.5f * pin) + 0.1 * (double)__expf(lv)) / (double)B_ROWS;
    }

    // ---- deterministic block tree reduction (double) ----
    __shared__ double sd[TPB];
    sd[threadIdx.x] = part;
    __syncthreads();
    #pragma unroll
    for (int s = TPB / 2; s > 0; s >>= 1) {
        if (threadIdx.x < s) sd[threadIdx.x] += sd[threadIdx.x + s];
        __syncthreads();
    }

    // ---- ticket: last block finalizes (deterministic fixed-order sum) ----
    __shared__ unsigned s_rank;
    if (threadIdx.x == 0) {
        g_partials[blockIdx.x] = sd[0];
        __threadfence();
        s_rank = atomicAdd(&g_ticket, 1u);
    }
    __syncthreads();
    if (s_rank == NBLOCKS - 1) {
        double s = 0.0;
        for (int i = threadIdx.x; i < NBLOCKS; i += TPB)
            s += __ldcg(&g_partials[i]);
        sd[threadIdx.x] = s;
        __syncthreads();
        #pragma unroll
        for (int k = TPB / 2; k > 0; k >>= 1) {
            if (threadIdx.x < k) sd[threadIdx.x] += sd[threadIdx.x + k];
            __syncthreads();
        }
        if (threadIdx.x == 0) {
            out[0] = (float)sd[0];
            atomicExch(&g_ticket, 0u);           // reset for next graph replay
        }
    }
}

extern "C" void kernel_launch(void* const* d_in, const int* in_sizes, int n_in,
                              void* d_out, int out_size) {
    const float* logits  = (const float*)d_in[0];
    const float* log_var = (const float*)d_in[1];
    const float* p_win   = (const float*)d_in[2];
    const int*   tgt32   = (const int*)d_in[3];
    float* out = (float*)d_out;

    loss_kernel<<<NBLOCKS, TPB>>>(logits, log_var, p_win, tgt32, out);
}

// round 13
// speedup vs baseline: 1.0034x; 1.0034x over previous
#include <cuda_runtime.h>
#include <stdint.h>

// ---------------------------------------------------------------------------
// DoctoralLoss fused single-kernel: MC aleatoric CE (T=100, exact JAX
// partitionable threefry + XLA erfinv) + 0.5*pinball(0.5) + 0.1*mean(exp(lv)).
// f32x2-packed float math (2 t-samples/iter), block-local dtype sniff,
// ticket-based last-block finalize.
// ---------------------------------------------------------------------------

#define T_SAMPLES 100
#define B_ROWS    131072
#define C_CLASSES 3
#define NCHUNK    5
#define TCHUNK    (T_SAMPLES / NCHUNK)    // 20
#define NPAIR     (TCHUNK / 2)            // 10
#define TPB       128
#define NTHREADS  (B_ROWS * NCHUNK)       // 655360
#define NBLOCKS   (NTHREADS / TPB)        // 5120
#define STRIDE    (B_ROWS * C_CLASSES)    // 393216

typedef unsigned long long u64_t;

__device__ double       g_partials[NBLOCKS];
__device__ unsigned int g_ticket = 0;

// ---------------- f32x2 helpers ----------------
__device__ __forceinline__ u64_t pk2(float lo, float hi) {
    u64_t r; asm("mov.b64 %0, {%1, %2};" : "=l"(r) : "f"(lo), "f"(hi)); return r;
}
__device__ __forceinline__ void upk2(u64_t v, float& lo, float& hi) {
    asm("mov.b64 {%0, %1}, %2;" : "=f"(lo), "=f"(hi) : "l"(v));
}
__device__ __forceinline__ u64_t fma2(u64_t a, u64_t b, u64_t c) {
    u64_t d; asm("fma.rn.f32x2 %0, %1, %2, %3;" : "=l"(d) : "l"(a), "l"(b), "l"(c)); return d;
}
__device__ __forceinline__ u64_t add2(u64_t a, u64_t b) {
    u64_t d; asm("add.rn.f32x2 %0, %1, %2;" : "=l"(d) : "l"(a), "l"(b)); return d;
}
__device__ __forceinline__ u64_t mul2(u64_t a, u64_t b) {
    u64_t d; asm("mul.rn.f32x2 %0, %1, %2;" : "=l"(d) : "l"(a), "l"(b)); return d;
}
// compile-time packable broadcast constant
__device__ __forceinline__ u64_t pkc(float v) {
    unsigned u = __float_as_uint(v);
    return ((u64_t)u << 32) | (u64_t)u;
}
__device__ __forceinline__ float ex2f(float x) {
    float r; asm("ex2.approx.f32 %0, %1;" : "=f"(r) : "f"(x)); return r;
}
__device__ __forceinline__ float lg2f(float x) {
    float r; asm("lg2.approx.f32 %0, %1;" : "=f"(r) : "f"(x)); return r;
}
__device__ __forceinline__ uint32_t rotl32(uint32_t v, int s) {
    return __funnelshift_l(v, v, s);
}

// ---------------- threefry2x32, key=(0,42), counter=(0,i), out = x0^x1 ------
__device__ __forceinline__ uint32_t threefry_bits(uint32_t i) {
    const uint32_t ks0 = 0u;
    const uint32_t ks1 = 42u;
    const uint32_t ks2 = 0x1BD11BDAu ^ 0u ^ 42u;

    uint32_t x0 = 0u + ks0;
    uint32_t x1 = i + ks1;

#define TF_ROUND(r) { x0 += x1; x1 = rotl32(x1, (r)); x1 ^= x0; }
#define TF_4ROUNDS(a,b,c,d) TF_ROUND(a) TF_ROUND(b) TF_ROUND(c) TF_ROUND(d)
    TF_4ROUNDS(13, 15, 26, 6)
    x0 += ks1; x1 += ks2 + 1u;
    TF_4ROUNDS(17, 29, 16, 24)
    x0 += ks2; x1 += ks0 + 2u;
    TF_4ROUNDS(13, 15, 26, 6)
    x0 += ks0; x1 += ks1 + 3u;
    TF_4ROUNDS(17, 29, 16, 24)
    x0 += ks1; x1 += ks2 + 4u;
    TF_4ROUNDS(13, 15, 26, 6)
    x0 += ks2; x1 += ks0 + 5u;
#undef TF_4ROUNDS
#undef TF_ROUND
    return x0 ^ x1;
}

// sqrt(2) folded into erfinv coefficients (<=2ulp per-sample vs reference)
#define SQ2 1.4142135623730951
#define CP(x) pkc((float)((x) * SQ2))

// rare-branch (w >= 5) scalar erfinv * sqrt2, times u
__device__ __forceinline__ float erfinv_rare(float w, float u) {
    float v = sqrtf(w) - 3.0f;
    float p =            (float)(-0.000200214257 * SQ2);
    p = fmaf(p, v,        (float)(0.000100950558 * SQ2));
    p = fmaf(p, v,        (float)(0.00134934322  * SQ2));
    p = fmaf(p, v,        (float)(-0.00367342844 * SQ2));
    p = fmaf(p, v,        (float)(0.00573950773  * SQ2));
    p = fmaf(p, v,        (float)(-0.0076224613  * SQ2));
    p = fmaf(p, v,        (float)(0.00943887047  * SQ2));
    p = fmaf(p, v,        (float)(1.00167406     * SQ2));
    p = fmaf(p, v,        (float)(2.83297682     * SQ2));
    return p * u;
}

// two threefry outputs -> packed pair of N(0,1) samples (sqrt2 folded)
__device__ __forceinline__ u64_t norm_pair(uint32_t ba, uint32_t bb) {
    const u64_t C_NEG1 = pkc(-1.0f);
    const u64_t C_TWO  = pkc(2.0f);
    const u64_t C_LO   = pkc(-0.99999994f);     // nextafter(-1,0)
    const u64_t C_ONE  = pkc(1.0f);
    const u64_t C_MLN2 = pkc((float)(-0.6931471805599453));
    const u64_t C_M25  = pkc(-2.5f);

    float fa = __uint_as_float((ba >> 9) | 0x3f800000u);   // [1,2)
    float fb = __uint_as_float((bb >> 9) | 0x3f800000u);
    u64_t F   = pk2(fa, fb);
    u64_t FM1 = add2(F, C_NEG1);                 // exact, in [0,1)
    u64_t U   = fma2(FM1, C_TWO, C_LO);          // uniform in [LO, 1); max(LO,.) redundant
    u64_t AP  = add2(U, C_ONE);                  // 1+x
    u64_t AM  = fma2(U, C_NEG1, C_ONE);          // 1-x (single rounding)
    u64_t TT  = mul2(AP, AM);                    // (1-x)(1+x) > 0
    float t0, t1; upk2(TT, t0, t1);
    u64_t LG  = pk2(lg2f(t0), lg2f(t1));
    u64_t W   = mul2(LG, C_MLN2);                // w = -log(t)
    u64_t S   = add2(W, C_M25);
    u64_t P   = CP(2.81022636e-08);
    P = fma2(P, S, CP(3.43273939e-07));
    P = fma2(P, S, CP(-3.5233877e-06));
    P = fma2(P, S, CP(-4.39150654e-06));
    P = fma2(P, S, CP(0.00021858087));
    P = fma2(P, S, CP(-0.00125372503));
    P = fma2(P, S, CP(-0.00417768164));
    P = fma2(P, S, CP(0.246640727));
    P = fma2(P, S, CP(1.50140941));
    u64_t R = mul2(P, U);                        // N(0,1) pair (sqrt2 folded)

    // rare tail: t <= e^-5  <=>  w >= 5
    const float T_TH = 6.7379470e-03f;
    if (__builtin_expect(__any_sync(0xffffffffu, fminf(t0, t1) <= T_TH), 0)) {
        float r0, r1, u0, u1, w0, w1;
        upk2(R, r0, r1); upk2(U, u0, u1); upk2(W, w0, w1);
        if (t0 <= T_TH) r0 = erfinv_rare(w0, u0);
        if (t1 <= T_TH) r1 = erfinv_rare(w1, u1);
        R = pk2(r0, r1);
    }
    return R;
}

__global__ __launch_bounds__(TPB) void loss_kernel(
    const float* __restrict__ logits,
    const float* __restrict__ log_var,
    const float* __restrict__ p_win,
    const int*   __restrict__ tgt32,
    float*       __restrict__ out)
{
    // ---- block-local dtype sniff: int64 targets have zero hi-words ----
    int probe = tgt32[2 * threadIdx.x + 1];
    bool is64 = (__syncthreads_count(probe != 0) == 0);

    int gid   = blockIdx.x * TPB + threadIdx.x;
    int b     = gid & (B_ROWS - 1);
    int chunk = gid >> 17;                        // B_ROWS = 2^17

    float l0 = logits[3 * b + 0];
    float l1 = logits[3 * b + 1];
    float l2 = logits[3 * b + 2];
    float lv   = log_var[b];
    float stdv = expf(0.5f * lv);
    int   tgt  = is64 ? tgt32[2 * b] : tgt32[b];

    const u64_t STD2  = pk2(stdv, stdv);
    const u64_t L02   = pk2(l0, l0);
    const u64_t L12   = pk2(l1, l1);
    const u64_t L22   = pk2(l2, l2);
    const u64_t C_NEG1 = pkc(-1.0f);
    const u64_t C_L2E  = pkc((float)1.4426950408889634);   // log2(e), same as __expf
    const float LN2F   = (float)0.6931471805599453;

    float accA = 0.0f, accB = 0.0f;
    uint32_t ctr = (uint32_t)(chunk * TCHUNK) * (uint32_t)STRIDE + (uint32_t)b * 3u;

    #pragma unroll 1
    for (int j = 0; j < NPAIR; ++j) {
        uint32_t iA = ctr;
        uint32_t iB = ctr + (uint32_t)STRIDE;
        ctr += 2u * (uint32_t)STRIDE;

        u64_t N0 = norm_pair(threefry_bits(iA),      threefry_bits(iB));
        u64_t N1 = norm_pair(threefry_bits(iA + 1u), threefry_bits(iB + 1u));
        u64_t N2 = norm_pair(threefry_bits(iA + 2u), threefry_bits(iB + 2u));

        u64_t D0 = fma2(N0, STD2, L02);
        u64_t D1 = fma2(N1, STD2, L12);
        u64_t D2 = fma2(N2, STD2, L22);

        float d0a, d0b, d1a, d1b, d2a, d2b;
        upk2(D0, d0a, d0b); upk2(D1, d1a, d1b); upk2(D2, d2a, d2b);
        float ma = fmaxf(d0a, fmaxf(d1a, d2a));
        float mb = fmaxf(d0b, fmaxf(d1b, d2b));
        u64_t M2v = pk2(ma, mb);

        u64_t E0 = mul2(fma2(M2v, C_NEG1, D0), C_L2E);   // (d-m)*log2e
        u64_t E1 = mul2(fma2(M2v, C_NEG1, D1), C_L2E);
        u64_t E2 = mul2(fma2(M2v, C_NEG1, D2), C_L2E);
        float e0a, e0b, e1a, e1b, e2a, e2b;
        upk2(E0, e0a, e0b); upk2(E1, e1a, e1b); upk2(E2, e2a, e2b);

        float sa = ex2f(e0a) + ex2f(e1a) + ex2f(e2a);
        float sb = ex2f(e0b) + ex2f(e1b) + ex2f(e2b);
        float lsea = fmaf(lg2f(sa), LN2F, ma);
        float lseb = fmaf(lg2f(sb), LN2F, mb);

        float dta = (tgt == 0) ? d0a : ((tgt == 1) ? d1a : d2a);
        float dtb = (tgt == 0) ? d0b : ((tgt == 1) ? d1b : d2b);
        accA += (lsea - dta);
        accB += (lseb - dtb);
    }

    double part = ((double)accA + (double)accB)
                * (1.0 / ((double)T_SAMPLES * (double)B_ROWS));

    if (chunk == 0) {
        int pred = 0; float mm = l0;
        if (l1 > mm) { mm = l1; pred = 1; }
        if (l2 > mm) { mm = l2; pred = 2; }
        float corr = (pred == tgt) ? 1.0f : 0.0f;
        float e    = corr - p_win[b];
        float pin  = 0.5f * fabsf(e);            // pinball, Q = 0.5
        part += ((double)(0.5f * pin) + 0.1 * (double)__expf(lv)) / (double)B_ROWS;
    }

    // ---- deterministic block tree reduction (double) ----
    __shared__ double sd[TPB];
    sd[threadIdx.x] = part;
    __syncthreads();
    #pragma unroll
    for (int s = TPB / 2; s > 0; s >>= 1) {
        if (threadIdx.x < s) sd[threadIdx.x] += sd[threadIdx.x + s];
        __syncthreads();
    }

    // ---- ticket: last block finalizes (deterministic fixed-order sum) ----
    __shared__ unsigned s_rank;
    if (threadIdx.x == 0) {
        g_partials[blockIdx.x] = sd[0];
        __threadfence();
        s_rank = atomicAdd(&g_ticket, 1u);
    }
    __syncthreads();
    if (s_rank == NBLOCKS - 1) {
        double s = 0.0;
        for (int i = threadIdx.x; i < NBLOCKS; i += TPB)
            s += __ldcg(&g_partials[i]);
        sd[threadIdx.x] = s;
        __syncthreads();
        #pragma unroll
        for (int k = TPB / 2; k > 0; k >>= 1) {
            if (threadIdx.x < k) sd[threadIdx.x] += sd[threadIdx.x + k];
            __syncthreads();
        }
        if (threadIdx.x == 0) {
            out[0] = (float)sd[0];
            atomicExch(&g_ticket, 0u);           // reset for next graph replay
        }
    }
}

extern "C" void kernel_launch(void* const* d_in, const int* in_sizes, int n_in,
                              void* d_out, int out_size) {
    const float* logits  = (const float*)d_in[0];
    const float* log_var = (const float*)d_in[1];
    const float* p_win   = (const float*)d_in[2];
    const int*   tgt32   = (const int*)d_in[3];
    float* out = (float*)d_out;

    loss_kernel<<<NBLOCKS, TPB>>>(logits, log_var, p_win, tgt32, out);
}